// round 3
// baseline (speedup 1.0000x reference)
#include <cuda_runtime.h>

#define NNODES 50000
#define NEDGES 800000
#define NF 128
#define NGRAPH 512
#define NCLS 10

// ---------------- device scratch (static: no allocations allowed) ----------
__device__ float g_h[NNODES * NF];     // layer activations
__device__ float g_hw[NNODES * NF];    // h @ W[l]
__device__ float g_dinv[NNODES];
__device__ int   g_deg[NNODES];
__device__ int   g_off[NNODES + 1];    // CSR offsets (incoming edges, excl self-loop)
__device__ int   g_cur[NNODES];        // fill cursors
__device__ int   g_row[NEDGES];        // CSR: source node per incoming edge
__device__ float g_pool[NGRAPH * NF];

// ---------------- init ----------
__global__ void k_zero() {
    int i = blockIdx.x * blockDim.x + threadIdx.x;
    if (i < NGRAPH * NF) g_pool[i] = 0.0f;
    if (i < NNODES) g_deg[i] = 0;
}

__global__ void k_count(const int* __restrict__ col) {
    int e = blockIdx.x * blockDim.x + threadIdx.x;
    if (e < NEDGES) {
        int c = col[e];
        c = min(max(c, 0), NNODES - 1);
        atomicAdd(&g_deg[c], 1);
    }
}

__global__ void k_dinv() {
    int i = blockIdx.x * blockDim.x + threadIdx.x;
    if (i < NNODES) g_dinv[i] = rsqrtf((float)(g_deg[i] + 1));  // +1 self-loop
}

// single-block chunked Hillis-Steele exclusive scan of g_deg -> g_off / g_cur
__global__ void k_scan() {
    __shared__ int s[1024];
    __shared__ int carry_s;
    int tid = threadIdx.x;
    if (tid == 0) carry_s = 0;
    __syncthreads();
    for (int base = 0; base < NNODES; base += 1024) {
        int i = base + tid;
        int v = (i < NNODES) ? g_deg[i] : 0;
        int carry = carry_s;
        s[tid] = v;
        __syncthreads();
        for (int d = 1; d < 1024; d <<= 1) {
            int t = (tid >= d) ? s[tid - d] : 0;
            __syncthreads();
            s[tid] += t;
            __syncthreads();
        }
        int incl = s[tid];
        int excl = incl - v;
        if (i < NNODES) { g_off[i] = carry + excl; g_cur[i] = carry + excl; }
        __syncthreads();
        if (tid == 1023) carry_s = carry + incl;
        __syncthreads();
    }
    if (tid == 0) g_off[NNODES] = carry_s;
}

__global__ void k_fill(const int* __restrict__ rowp,
                       const int* __restrict__ colp) {
    int e = blockIdx.x * blockDim.x + threadIdx.x;
    if (e < NEDGES) {
        int c = colp[e];
        c = min(max(c, 0), NNODES - 1);
        int r = rowp[e];
        r = min(max(r, 0), NNODES - 1);
        int p = atomicAdd(&g_cur[c], 1);
        if (p >= 0 && p < NEDGES) g_row[p] = r;
    }
}

// ---------------- GEMM: g_hw = A @ W[layer], A = x (layer 0) or g_h --------
__global__ __launch_bounds__(256) void k_gemm(const float* __restrict__ x,
                                              const float* __restrict__ Wall,
                                              int layer) {
    __shared__ float As[16][128];   // transposed: As[k][m]
    __shared__ float Bs[16][128];   // Bs[k][n]

    const float* __restrict__ A = (layer == 0) ? x : (const float*)g_h;
    const float* __restrict__ B = Wall + (size_t)layer * NF * NF;
    float* __restrict__ C = g_hw;

    int bm = blockIdx.x * 128;
    int tid = threadIdx.x;
    int tx = tid & 15;   // column group
    int ty = tid >> 4;   // row group

    float acc[8][8];
#pragma unroll
    for (int j = 0; j < 8; j++)
#pragma unroll
        for (int jj = 0; jj < 8; jj++) acc[j][jj] = 0.0f;

    for (int k0 = 0; k0 < 128; k0 += 16) {
        // load A tile (128 rows x 16 k), transposed into As
#pragma unroll
        for (int i = 0; i < 2; i++) {
            int f = tid * 2 + i;          // 0..511
            int r = f >> 2;               // 0..127
            int kq = f & 3;               // 0..3 (each = 4 k's)
            float4 v = make_float4(0.f, 0.f, 0.f, 0.f);
            if (bm + r < NNODES)
                v = *(const float4*)(A + (size_t)(bm + r) * NF + k0 + kq * 4);
            As[kq * 4 + 0][r] = v.x;
            As[kq * 4 + 1][r] = v.y;
            As[kq * 4 + 2][r] = v.z;
            As[kq * 4 + 3][r] = v.w;
        }
        // load B tile (16 k x 128 n)
#pragma unroll
        for (int i = 0; i < 2; i++) {
            int f = tid * 2 + i;
            int kr = f >> 5;              // 0..15
            int cq = f & 31;              // 0..31
            *(float4*)(&Bs[kr][cq * 4]) =
                *(const float4*)(B + (size_t)(k0 + kr) * NF + cq * 4);
        }
        __syncthreads();

#pragma unroll
        for (int kk = 0; kk < 16; kk++) {
            float a[8], bb[8];
            *(float4*)(a)     = *(const float4*)(&As[kk][ty * 8]);
            *(float4*)(a + 4) = *(const float4*)(&As[kk][ty * 8 + 4]);
            *(float4*)(bb)     = *(const float4*)(&Bs[kk][tx * 8]);
            *(float4*)(bb + 4) = *(const float4*)(&Bs[kk][tx * 8 + 4]);
#pragma unroll
            for (int j = 0; j < 8; j++)
#pragma unroll
                for (int jj = 0; jj < 8; jj++)
                    acc[j][jj] += a[j] * bb[jj];
        }
        __syncthreads();
    }

#pragma unroll
    for (int j = 0; j < 8; j++) {
        int row = bm + ty * 8 + j;
        if (row < NNODES) {
            *(float4*)(C + (size_t)row * NF + tx * 8) =
                make_float4(acc[j][0], acc[j][1], acc[j][2], acc[j][3]);
            *(float4*)(C + (size_t)row * NF + tx * 8 + 4) =
                make_float4(acc[j][4], acc[j][5], acc[j][6], acc[j][7]);
        }
    }
}

// ---------------- gather + self-loop + bias + relu -> g_h ------------------
__global__ __launch_bounds__(256) void k_gather(const float* __restrict__ ball,
                                                int layer) {
    int node = blockIdx.x * 8 + (threadIdx.x >> 5);
    if (node >= NNODES) return;
    int lane = threadIdx.x & 31;

    const float* __restrict__ hw = g_hw;
    const float* __restrict__ bias = ball + layer * NF;

    float di = g_dinv[node];
    float4 acc = make_float4(0.f, 0.f, 0.f, 0.f);
    int s = g_off[node];
    int e = g_off[node + 1];
    for (int p = s; p < e; p++) {
        int r = g_row[p];
        float nm = di * g_dinv[r];
        float4 v = *(const float4*)(hw + (size_t)r * NF + lane * 4);
        acc.x += v.x * nm;
        acc.y += v.y * nm;
        acc.z += v.z * nm;
        acc.w += v.w * nm;
    }
    // self-loop
    {
        float nm = di * di;
        float4 v = *(const float4*)(hw + (size_t)node * NF + lane * 4);
        acc.x += v.x * nm;
        acc.y += v.y * nm;
        acc.z += v.z * nm;
        acc.w += v.w * nm;
    }
    float4 bb = *(const float4*)(bias + lane * 4);
    acc.x = fmaxf(acc.x + bb.x, 0.f);
    acc.y = fmaxf(acc.y + bb.y, 0.f);
    acc.z = fmaxf(acc.z + bb.z, 0.f);
    acc.w = fmaxf(acc.w + bb.w, 0.f);
    *(float4*)(g_h + (size_t)node * NF + lane * 4) = acc;
}

// ---------------- global add pool ----------
__global__ __launch_bounds__(256) void k_pool(const int* __restrict__ batch) {
    int node = blockIdx.x * 8 + (threadIdx.x >> 5);
    if (node >= NNODES) return;
    int lane = threadIdx.x & 31;
    int g = batch[node];
    g = min(max(g, 0), NGRAPH - 1);
    float4 v = *(const float4*)(g_h + (size_t)node * NF + lane * 4);
    float* dst = g_pool + (size_t)g * NF + lane * 4;
    atomicAdd(dst + 0, v.x);
    atomicAdd(dst + 1, v.y);
    atomicAdd(dst + 2, v.z);
    atomicAdd(dst + 3, v.w);
}

// ---------------- output head: out = pool @ W_out + b_out ------------------
__global__ __launch_bounds__(128) void k_out(const float* __restrict__ Wout,
                                             const float* __restrict__ bout,
                                             float* __restrict__ out) {
    int w = blockIdx.x * 4 + (threadIdx.x >> 5);
    if (w >= NGRAPH) return;
    int lane = threadIdx.x & 31;
    float4 p = *(const float4*)(g_pool + (size_t)w * NF + lane * 4);
#pragma unroll
    for (int c = 0; c < NCLS; c++) {
        float sum = p.x * Wout[(lane * 4 + 0) * NCLS + c]
                  + p.y * Wout[(lane * 4 + 1) * NCLS + c]
                  + p.z * Wout[(lane * 4 + 2) * NCLS + c]
                  + p.w * Wout[(lane * 4 + 3) * NCLS + c];
#pragma unroll
        for (int o = 16; o > 0; o >>= 1)
            sum += __shfl_down_sync(0xffffffffu, sum, o);
        if (lane == 0) out[w * NCLS + c] = sum + bout[c];
    }
}

// ---------------- launch ----------
extern "C" void kernel_launch(void* const* d_in, const int* in_sizes, int n_in,
                              void* d_out, int out_size) {
    // Identify inputs by element count (all pairwise distinct) — immune to
    // metadata ordering:
    //   x: 6,400,000  edge_index: 1,600,000  batch: 50,000
    //   W: 49,152     b: 384                 W_out: 1,280   b_out: 10
    // NOTE: JAX default config has x64 disabled -> edge_index/batch are int32.
    const float* x     = nullptr;
    const int*   ei    = nullptr;
    const int*   batch = nullptr;
    const float* W     = nullptr;
    const float* b     = nullptr;
    const float* Wout  = nullptr;
    const float* bout  = nullptr;
    for (int i = 0; i < n_in; i++) {
        switch (in_sizes[i]) {
            case NNODES * NF:      x     = (const float*)d_in[i]; break;
            case 2 * NEDGES:       ei    = (const int*)d_in[i];   break;
            case NNODES:           batch = (const int*)d_in[i];   break;
            case 3 * NF * NF:      W     = (const float*)d_in[i]; break;
            case 3 * NF:           b     = (const float*)d_in[i]; break;
            case NF * NCLS:        Wout  = (const float*)d_in[i]; break;
            case NCLS:             bout  = (const float*)d_in[i]; break;
            default: break;
        }
    }
    float* out = (float*)d_out;

    const int* rowp = ei;           // source nodes j
    const int* colp = ei + NEDGES;  // target nodes i

    k_zero<<<(NGRAPH * NF + 255) / 256, 256>>>();
    k_count<<<(NEDGES + 255) / 256, 256>>>(colp);
    k_dinv<<<(NNODES + 255) / 256, 256>>>();
    k_scan<<<1, 1024>>>();
    k_fill<<<(NEDGES + 255) / 256, 256>>>(rowp, colp);

    for (int l = 0; l < 3; l++) {
        k_gemm<<<(NNODES + 127) / 128, 256>>>(x, W, l);
        k_gather<<<(NNODES + 7) / 8, 256>>>(b, l);
    }

    k_pool<<<(NNODES + 7) / 8, 256>>>(batch);
    k_out<<<NGRAPH / 4, 128>>>(Wout, bout, out);
}

// round 4
// speedup vs baseline: 1.2474x; 1.2474x over previous
#include <cuda_runtime.h>

#define NNODES 50000
#define NEDGES 800000
#define NF 128
#define NGRAPH 512
#define NCLS 10
#define SCAN_BLOCKS ((NNODES + 1023) / 1024)   // 49

// ---------------- device scratch (static: no allocations allowed) ----------
__device__ float g_h[NNODES * NF];     // layer activations
__device__ float g_hw[NNODES * NF];    // h @ W[l]
__device__ float g_dinv[NNODES];
__device__ int   g_deg[NNODES];
__device__ int   g_off[NNODES + 1];    // CSR offsets (incoming edges, excl self-loop)
__device__ int   g_cur[NNODES];        // fill cursors
__device__ int   g_row[NEDGES];        // CSR: source node per incoming edge
__device__ float g_pool[NGRAPH * NF];
__device__ int   g_bsum[SCAN_BLOCKS];  // per-block degree sums
__device__ int   g_boff[SCAN_BLOCKS];  // scanned block offsets

// ---------------- init ----------
__global__ void k_zero() {
    int i = blockIdx.x * blockDim.x + threadIdx.x;
    if (i < NGRAPH * NF) g_pool[i] = 0.0f;
    if (i < NNODES) g_deg[i] = 0;
}

__global__ void k_count(const int* __restrict__ col) {
    int e = blockIdx.x * blockDim.x + threadIdx.x;
    if (e < NEDGES) {
        int c = col[e];
        c = min(max(c, 0), NNODES - 1);
        atomicAdd(&g_deg[c], 1);
    }
}

__global__ void k_dinv() {
    int i = blockIdx.x * blockDim.x + threadIdx.x;
    if (i < NNODES) g_dinv[i] = rsqrtf((float)(g_deg[i] + 1));  // +1 self-loop
}

// ---------- 3-stage parallel exclusive scan of g_deg -> g_off / g_cur ------
// Stage A: per-block (1024-wide) local exclusive scan via warp shuffles
__global__ __launch_bounds__(1024) void k_scan_a() {
    int i = blockIdx.x * 1024 + threadIdx.x;
    int lane = threadIdx.x & 31;
    int wid = threadIdx.x >> 5;
    int v = (i < NNODES) ? g_deg[i] : 0;

    int incl = v;
#pragma unroll
    for (int d = 1; d < 32; d <<= 1) {
        int t = __shfl_up_sync(0xffffffffu, incl, d);
        if (lane >= d) incl += t;
    }
    __shared__ int wsum[32];
    if (lane == 31) wsum[wid] = incl;
    __syncthreads();
    if (wid == 0) {
        int s = wsum[lane];
#pragma unroll
        for (int d = 1; d < 32; d <<= 1) {
            int t = __shfl_up_sync(0xffffffffu, s, d);
            if (lane >= d) s += t;
        }
        wsum[lane] = s;
    }
    __syncthreads();
    int warpoff = (wid > 0) ? wsum[wid - 1] : 0;
    int excl = warpoff + incl - v;
    if (i < NNODES) g_off[i] = excl;               // block-local exclusive
    if (threadIdx.x == 1023) g_bsum[blockIdx.x] = warpoff + incl;
}

// Stage B: scan the 49 block sums (one 64-thread block)
__global__ void k_scan_b() {
    __shared__ int s[64];
    int tid = threadIdx.x;
    int v = (tid < SCAN_BLOCKS) ? g_bsum[tid] : 0;
    s[tid] = v;
    __syncthreads();
#pragma unroll
    for (int d = 1; d < 64; d <<= 1) {
        int t = (tid >= d) ? s[tid - d] : 0;
        __syncthreads();
        s[tid] += t;
        __syncthreads();
    }
    if (tid < SCAN_BLOCKS) g_boff[tid] = s[tid] - v;   // exclusive
    if (tid == 0) g_off[NNODES] = NEDGES;              // total degree is static
}

// Stage C: add block offsets, materialize cursors
__global__ __launch_bounds__(1024) void k_scan_c() {
    int i = blockIdx.x * 1024 + threadIdx.x;
    if (i < NNODES) {
        int o = g_off[i] + g_boff[blockIdx.x];
        g_off[i] = o;
        g_cur[i] = o;
    }
}

__global__ void k_fill(const int* __restrict__ rowp,
                       const int* __restrict__ colp) {
    int e = blockIdx.x * blockDim.x + threadIdx.x;
    if (e < NEDGES) {
        int c = colp[e];
        c = min(max(c, 0), NNODES - 1);
        int r = rowp[e];
        r = min(max(r, 0), NNODES - 1);
        int p = atomicAdd(&g_cur[c], 1);
        if (p >= 0 && p < NEDGES) g_row[p] = r;
    }
}

// ---------------- GEMM: g_hw = A @ W[layer], A = x (layer 0) or g_h --------
__global__ __launch_bounds__(256) void k_gemm(const float* __restrict__ x,
                                              const float* __restrict__ Wall,
                                              int layer) {
    __shared__ float As[16][128];   // transposed: As[k][m]
    __shared__ float Bs[16][128];   // Bs[k][n]

    const float* __restrict__ A = (layer == 0) ? x : (const float*)g_h;
    const float* __restrict__ B = Wall + (size_t)layer * NF * NF;
    float* __restrict__ C = g_hw;

    int bm = blockIdx.x * 128;
    int tid = threadIdx.x;
    int tx = tid & 15;   // column group
    int ty = tid >> 4;   // row group

    float acc[8][8];
#pragma unroll
    for (int j = 0; j < 8; j++)
#pragma unroll
        for (int jj = 0; jj < 8; jj++) acc[j][jj] = 0.0f;

    for (int k0 = 0; k0 < 128; k0 += 16) {
        // load A tile (128 rows x 16 k), transposed into As
#pragma unroll
        for (int i = 0; i < 2; i++) {
            int f = tid * 2 + i;          // 0..511
            int r = f >> 2;               // 0..127
            int kq = f & 3;               // 0..3 (each = 4 k's)
            float4 v = make_float4(0.f, 0.f, 0.f, 0.f);
            if (bm + r < NNODES)
                v = *(const float4*)(A + (size_t)(bm + r) * NF + k0 + kq * 4);
            As[kq * 4 + 0][r] = v.x;
            As[kq * 4 + 1][r] = v.y;
            As[kq * 4 + 2][r] = v.z;
            As[kq * 4 + 3][r] = v.w;
        }
        // load B tile (16 k x 128 n)
#pragma unroll
        for (int i = 0; i < 2; i++) {
            int f = tid * 2 + i;
            int kr = f >> 5;              // 0..15
            int cq = f & 31;              // 0..31
            *(float4*)(&Bs[kr][cq * 4]) =
                *(const float4*)(B + (size_t)(k0 + kr) * NF + cq * 4);
        }
        __syncthreads();

#pragma unroll
        for (int kk = 0; kk < 16; kk++) {
            float a[8], bb[8];
            *(float4*)(a)     = *(const float4*)(&As[kk][ty * 8]);
            *(float4*)(a + 4) = *(const float4*)(&As[kk][ty * 8 + 4]);
            *(float4*)(bb)     = *(const float4*)(&Bs[kk][tx * 8]);
            *(float4*)(bb + 4) = *(const float4*)(&Bs[kk][tx * 8 + 4]);
#pragma unroll
            for (int j = 0; j < 8; j++)
#pragma unroll
                for (int jj = 0; jj < 8; jj++)
                    acc[j][jj] += a[j] * bb[jj];
        }
        __syncthreads();
    }

#pragma unroll
    for (int j = 0; j < 8; j++) {
        int row = bm + ty * 8 + j;
        if (row < NNODES) {
            *(float4*)(C + (size_t)row * NF + tx * 8) =
                make_float4(acc[j][0], acc[j][1], acc[j][2], acc[j][3]);
            *(float4*)(C + (size_t)row * NF + tx * 8 + 4) =
                make_float4(acc[j][4], acc[j][5], acc[j][6], acc[j][7]);
        }
    }
}

// ------- gather + self-loop + bias + relu -> g_h (or pooled atomicAdd) -----
template <bool DO_POOL>
__global__ __launch_bounds__(256) void k_gather(const float* __restrict__ ball,
                                                int layer,
                                                const int* __restrict__ batch) {
    int node = blockIdx.x * 8 + (threadIdx.x >> 5);
    if (node >= NNODES) return;
    int lane = threadIdx.x & 31;

    const float* __restrict__ hw = g_hw;
    const float* __restrict__ bias = ball + layer * NF;

    float di = g_dinv[node];
    float4 acc = make_float4(0.f, 0.f, 0.f, 0.f);
    int s = g_off[node];
    int e = g_off[node + 1];
    for (int p = s; p < e; p++) {
        int r = g_row[p];
        float nm = di * g_dinv[r];
        float4 v = *(const float4*)(hw + (size_t)r * NF + lane * 4);
        acc.x += v.x * nm;
        acc.y += v.y * nm;
        acc.z += v.z * nm;
        acc.w += v.w * nm;
    }
    // self-loop
    {
        float nm = di * di;
        float4 v = *(const float4*)(hw + (size_t)node * NF + lane * 4);
        acc.x += v.x * nm;
        acc.y += v.y * nm;
        acc.z += v.z * nm;
        acc.w += v.w * nm;
    }
    float4 bb = *(const float4*)(bias + lane * 4);
    acc.x = fmaxf(acc.x + bb.x, 0.f);
    acc.y = fmaxf(acc.y + bb.y, 0.f);
    acc.z = fmaxf(acc.z + bb.z, 0.f);
    acc.w = fmaxf(acc.w + bb.w, 0.f);

    if (DO_POOL) {
        int g = batch[node];
        g = min(max(g, 0), NGRAPH - 1);
        float* dst = g_pool + (size_t)g * NF + lane * 4;
        atomicAdd(dst + 0, acc.x);
        atomicAdd(dst + 1, acc.y);
        atomicAdd(dst + 2, acc.z);
        atomicAdd(dst + 3, acc.w);
    } else {
        *(float4*)(g_h + (size_t)node * NF + lane * 4) = acc;
    }
}

// ---------------- output head: out = pool @ W_out + b_out ------------------
__global__ __launch_bounds__(128) void k_out(const float* __restrict__ Wout,
                                             const float* __restrict__ bout,
                                             float* __restrict__ out) {
    int w = blockIdx.x * 4 + (threadIdx.x >> 5);
    if (w >= NGRAPH) return;
    int lane = threadIdx.x & 31;
    float4 p = *(const float4*)(g_pool + (size_t)w * NF + lane * 4);
#pragma unroll
    for (int c = 0; c < NCLS; c++) {
        float sum = p.x * Wout[(lane * 4 + 0) * NCLS + c]
                  + p.y * Wout[(lane * 4 + 1) * NCLS + c]
                  + p.z * Wout[(lane * 4 + 2) * NCLS + c]
                  + p.w * Wout[(lane * 4 + 3) * NCLS + c];
#pragma unroll
        for (int o = 16; o > 0; o >>= 1)
            sum += __shfl_down_sync(0xffffffffu, sum, o);
        if (lane == 0) out[w * NCLS + c] = sum + bout[c];
    }
}

// ---------------- launch ----------
extern "C" void kernel_launch(void* const* d_in, const int* in_sizes, int n_in,
                              void* d_out, int out_size) {
    // Identify inputs by element count (all pairwise distinct):
    //   x: 6,400,000  edge_index: 1,600,000  batch: 50,000
    //   W: 49,152     b: 384                 W_out: 1,280   b_out: 10
    // edge_index/batch are int32 (JAX x64 disabled).
    const float* x     = nullptr;
    const int*   ei    = nullptr;
    const int*   batch = nullptr;
    const float* W     = nullptr;
    const float* b     = nullptr;
    const float* Wout  = nullptr;
    const float* bout  = nullptr;
    for (int i = 0; i < n_in; i++) {
        switch (in_sizes[i]) {
            case NNODES * NF:      x     = (const float*)d_in[i]; break;
            case 2 * NEDGES:       ei    = (const int*)d_in[i];   break;
            case NNODES:           batch = (const int*)d_in[i];   break;
            case 3 * NF * NF:      W     = (const float*)d_in[i]; break;
            case 3 * NF:           b     = (const float*)d_in[i]; break;
            case NF * NCLS:        Wout  = (const float*)d_in[i]; break;
            case NCLS:             bout  = (const float*)d_in[i]; break;
            default: break;
        }
    }
    float* out = (float*)d_out;

    const int* rowp = ei;           // source nodes j
    const int* colp = ei + NEDGES;  // target nodes i

    k_zero<<<(NGRAPH * NF + 255) / 256, 256>>>();
    k_count<<<(NEDGES + 255) / 256, 256>>>(colp);
    k_dinv<<<(NNODES + 255) / 256, 256>>>();
    k_scan_a<<<SCAN_BLOCKS, 1024>>>();
    k_scan_b<<<1, 64>>>();
    k_scan_c<<<SCAN_BLOCKS, 1024>>>();
    k_fill<<<(NEDGES + 255) / 256, 256>>>(rowp, colp);

    for (int l = 0; l < 3; l++) {
        k_gemm<<<(NNODES + 127) / 128, 256>>>(x, W, l);
        if (l < 2)
            k_gather<false><<<(NNODES + 7) / 8, 256>>>(b, l, batch);
        else
            k_gather<true><<<(NNODES + 7) / 8, 256>>>(b, l, batch);
    }

    k_out<<<NGRAPH / 4, 128>>>(Wout, bout, out);
}

// round 5
// speedup vs baseline: 1.5141x; 1.2138x over previous
#include <cuda_runtime.h>
#include <cstdint>

#define NNODES 50000
#define NEDGES 800000
#define NF 128
#define NGRAPH 512
#define NCLS 10
#define SCAN_BLOCKS ((NNODES + 1023) / 1024)   // 49

// ---------------- device scratch (static: no allocations allowed) ----------
__device__ float g_h[NNODES * NF];     // layer activations
__device__ float g_hw[NNODES * NF];    // h @ W[l]
__device__ float g_dinv[NNODES];
__device__ int   g_deg[NNODES];
__device__ int   g_off[NNODES + 1];    // CSR offsets (incoming edges, excl self-loop)
__device__ int   g_cur[NNODES];        // fill cursors
__device__ int   g_row[NEDGES];        // CSR: source node per incoming edge
__device__ float g_pool[NGRAPH * NF];
__device__ int   g_bsum[SCAN_BLOCKS];  // per-block degree sums
__device__ int   g_boff[SCAN_BLOCKS];  // scanned block offsets

// ---------------- init ----------
__global__ void k_zero() {
    int i = blockIdx.x * blockDim.x + threadIdx.x;
    if (i < NGRAPH * NF) g_pool[i] = 0.0f;
    if (i < NNODES) g_deg[i] = 0;
}

__global__ void k_count(const int* __restrict__ col) {
    int e = blockIdx.x * blockDim.x + threadIdx.x;
    if (e < NEDGES) {
        int c = col[e];
        c = min(max(c, 0), NNODES - 1);
        atomicAdd(&g_deg[c], 1);
    }
}

__global__ void k_dinv() {
    int i = blockIdx.x * blockDim.x + threadIdx.x;
    if (i < NNODES) g_dinv[i] = rsqrtf((float)(g_deg[i] + 1));  // +1 self-loop
}

// ---------- 3-stage parallel exclusive scan of g_deg -> g_off / g_cur ------
__global__ __launch_bounds__(1024) void k_scan_a() {
    int i = blockIdx.x * 1024 + threadIdx.x;
    int lane = threadIdx.x & 31;
    int wid = threadIdx.x >> 5;
    int v = (i < NNODES) ? g_deg[i] : 0;

    int incl = v;
#pragma unroll
    for (int d = 1; d < 32; d <<= 1) {
        int t = __shfl_up_sync(0xffffffffu, incl, d);
        if (lane >= d) incl += t;
    }
    __shared__ int wsum[32];
    if (lane == 31) wsum[wid] = incl;
    __syncthreads();
    if (wid == 0) {
        int s = wsum[lane];
#pragma unroll
        for (int d = 1; d < 32; d <<= 1) {
            int t = __shfl_up_sync(0xffffffffu, s, d);
            if (lane >= d) s += t;
        }
        wsum[lane] = s;
    }
    __syncthreads();
    int warpoff = (wid > 0) ? wsum[wid - 1] : 0;
    int excl = warpoff + incl - v;
    if (i < NNODES) g_off[i] = excl;               // block-local exclusive
    if (threadIdx.x == 1023) g_bsum[blockIdx.x] = warpoff + incl;
}

__global__ void k_scan_b() {
    __shared__ int s[64];
    int tid = threadIdx.x;
    int v = (tid < SCAN_BLOCKS) ? g_bsum[tid] : 0;
    s[tid] = v;
    __syncthreads();
#pragma unroll
    for (int d = 1; d < 64; d <<= 1) {
        int t = (tid >= d) ? s[tid - d] : 0;
        __syncthreads();
        s[tid] += t;
        __syncthreads();
    }
    if (tid < SCAN_BLOCKS) g_boff[tid] = s[tid] - v;   // exclusive
    if (tid == 0) g_off[NNODES] = NEDGES;              // total degree is static
}

__global__ __launch_bounds__(1024) void k_scan_c() {
    int i = blockIdx.x * 1024 + threadIdx.x;
    if (i < NNODES) {
        int o = g_off[i] + g_boff[blockIdx.x];
        g_off[i] = o;
        g_cur[i] = o;
    }
}

__global__ void k_fill(const int* __restrict__ rowp,
                       const int* __restrict__ colp) {
    int e = blockIdx.x * blockDim.x + threadIdx.x;
    if (e < NEDGES) {
        int c = colp[e];
        c = min(max(c, 0), NNODES - 1);
        int r = rowp[e];
        r = min(max(r, 0), NNODES - 1);
        int p = atomicAdd(&g_cur[c], 1);
        if (p >= 0 && p < NEDGES) g_row[p] = r;
    }
}

// ---------------- tf32 helpers ----------------
__device__ __forceinline__ uint32_t f2tf32(float v) {
    uint32_t r;
    asm("cvt.rna.tf32.f32 %0, %1;" : "=r"(r) : "f"(v));
    return r;
}
__device__ __forceinline__ void split_tf32(float v, uint32_t& hi, uint32_t& lo) {
    hi = f2tf32(v);
    float hif = __uint_as_float(hi);
    lo = f2tf32(v - hif);
}
__device__ __forceinline__ void mma_tf32(float* c, const uint32_t* a,
                                         uint32_t b0, uint32_t b1) {
    asm volatile(
        "mma.sync.aligned.m16n8k8.row.col.f32.tf32.tf32.f32 "
        "{%0,%1,%2,%3}, {%4,%5,%6,%7}, {%8,%9}, {%0,%1,%2,%3};"
        : "+f"(c[0]), "+f"(c[1]), "+f"(c[2]), "+f"(c[3])
        : "r"(a[0]), "r"(a[1]), "r"(a[2]), "r"(a[3]), "r"(b0), "r"(b1));
}

// -------- GEMM (tf32 tensor cores, 3xTF32 compensated): g_hw = A @ W[l] ----
// Block tile 128x128, 8 warps, each warp 32(m) x 64(n). K loop in slices of 32.
__global__ __launch_bounds__(256) void k_gemm(const float* __restrict__ x,
                                              const float* __restrict__ Wall,
                                              int layer) {
    __shared__ float As[128][36];   // 128 rows x 32 k (+4 pad: conflict-free frags)
    __shared__ float Ws[32][136];   // 32 k x 128 n   (+8 pad: conflict-free frags)

    const float* __restrict__ A = (layer == 0) ? x : (const float*)g_h;
    const float* __restrict__ B = Wall + (size_t)layer * NF * NF;
    float* __restrict__ C = g_hw;

    int bm = blockIdx.x * 128;
    int tid = threadIdx.x;
    int warp = tid >> 5, lane = tid & 31;
    int wr = warp >> 1;        // 0..3 -> 32-row slab
    int wc = warp & 1;         // 0..1 -> 64-col slab
    int g = lane >> 2;         // groupID 0..7
    int tig = lane & 3;        // threadID_in_group 0..3

    float acc[2][8][4];
#pragma unroll
    for (int ti = 0; ti < 2; ti++)
#pragma unroll
        for (int tj = 0; tj < 8; tj++)
#pragma unroll
            for (int q = 0; q < 4; q++) acc[ti][tj][q] = 0.0f;

    for (int k0 = 0; k0 < NF; k0 += 32) {
        // load A tile: 128x32 floats = 1024 float4
#pragma unroll
        for (int i = 0; i < 4; i++) {
            int e = tid + i * 256;
            int row = e >> 3;
            int kq = (e & 7) * 4;
            float4 v = make_float4(0.f, 0.f, 0.f, 0.f);
            if (bm + row < NNODES)
                v = *(const float4*)(A + (size_t)(bm + row) * NF + k0 + kq);
            As[row][kq + 0] = v.x;
            As[row][kq + 1] = v.y;
            As[row][kq + 2] = v.z;
            As[row][kq + 3] = v.w;
        }
        // load W tile: 32x128 floats = 1024 float4
#pragma unroll
        for (int i = 0; i < 4; i++) {
            int e = tid + i * 256;
            int kr = e >> 5;
            int cq = (e & 31) * 4;
            float4 v = *(const float4*)(B + (size_t)(k0 + kr) * NF + cq);
            Ws[kr][cq + 0] = v.x;
            Ws[kr][cq + 1] = v.y;
            Ws[kr][cq + 2] = v.z;
            Ws[kr][cq + 3] = v.w;
        }
        __syncthreads();

#pragma unroll
        for (int kk = 0; kk < 32; kk += 8) {
            // A fragments (2 m16 tiles)
            uint32_t ahi[2][4], alo[2][4];
#pragma unroll
            for (int ti = 0; ti < 2; ti++) {
                int r0 = wr * 32 + ti * 16 + g;
                split_tf32(As[r0][kk + tig],         ahi[ti][0], alo[ti][0]);
                split_tf32(As[r0 + 8][kk + tig],     ahi[ti][1], alo[ti][1]);
                split_tf32(As[r0][kk + tig + 4],     ahi[ti][2], alo[ti][2]);
                split_tf32(As[r0 + 8][kk + tig + 4], ahi[ti][3], alo[ti][3]);
            }
            // B fragments (8 n8 tiles), consumed immediately
#pragma unroll
            for (int tj = 0; tj < 8; tj++) {
                int n0 = wc * 64 + tj * 8 + g;
                uint32_t bhi0, blo0, bhi1, blo1;
                split_tf32(Ws[kk + tig][n0],     bhi0, blo0);
                split_tf32(Ws[kk + tig + 4][n0], bhi1, blo1);
#pragma unroll
                for (int ti = 0; ti < 2; ti++) {
                    mma_tf32(acc[ti][tj], ahi[ti], bhi0, bhi1);  // hi*hi
                    mma_tf32(acc[ti][tj], alo[ti], bhi0, bhi1);  // lo*hi
                    mma_tf32(acc[ti][tj], ahi[ti], blo0, blo1);  // hi*lo
                }
            }
        }
        __syncthreads();
    }

    // store C
#pragma unroll
    for (int ti = 0; ti < 2; ti++) {
#pragma unroll
        for (int tj = 0; tj < 8; tj++) {
            int row = bm + wr * 32 + ti * 16 + g;
            int col = wc * 64 + tj * 8 + tig * 2;
            if (row < NNODES)
                *(float2*)(C + (size_t)row * NF + col) =
                    make_float2(acc[ti][tj][0], acc[ti][tj][1]);
            if (row + 8 < NNODES)
                *(float2*)(C + (size_t)(row + 8) * NF + col) =
                    make_float2(acc[ti][tj][2], acc[ti][tj][3]);
        }
    }
}

// ------- gather + self-loop + bias + relu -> g_h (or pooled atomicAdd) -----
template <bool DO_POOL>
__global__ __launch_bounds__(256) void k_gather(const float* __restrict__ ball,
                                                int layer,
                                                const int* __restrict__ batch) {
    int node = blockIdx.x * 8 + (threadIdx.x >> 5);
    if (node >= NNODES) return;
    int lane = threadIdx.x & 31;

    const float* __restrict__ hw = g_hw;
    const float* __restrict__ bias = ball + layer * NF;

    float di = g_dinv[node];
    float4 acc = make_float4(0.f, 0.f, 0.f, 0.f);
    int s = g_off[node];
    int e = g_off[node + 1];
    for (int p = s; p < e; p++) {
        int r = g_row[p];
        float nm = di * g_dinv[r];
        float4 v = *(const float4*)(hw + (size_t)r * NF + lane * 4);
        acc.x += v.x * nm;
        acc.y += v.y * nm;
        acc.z += v.z * nm;
        acc.w += v.w * nm;
    }
    // self-loop
    {
        float nm = di * di;
        float4 v = *(const float4*)(hw + (size_t)node * NF + lane * 4);
        acc.x += v.x * nm;
        acc.y += v.y * nm;
        acc.z += v.z * nm;
        acc.w += v.w * nm;
    }
    float4 bb = *(const float4*)(bias + lane * 4);
    acc.x = fmaxf(acc.x + bb.x, 0.f);
    acc.y = fmaxf(acc.y + bb.y, 0.f);
    acc.z = fmaxf(acc.z + bb.z, 0.f);
    acc.w = fmaxf(acc.w + bb.w, 0.f);

    if (DO_POOL) {
        int gph = batch[node];
        gph = min(max(gph, 0), NGRAPH - 1);
        float* dst = g_pool + (size_t)gph * NF + lane * 4;
        atomicAdd(dst + 0, acc.x);
        atomicAdd(dst + 1, acc.y);
        atomicAdd(dst + 2, acc.z);
        atomicAdd(dst + 3, acc.w);
    } else {
        *(float4*)(g_h + (size_t)node * NF + lane * 4) = acc;
    }
}

// ---------------- output head: out = pool @ W_out + b_out ------------------
__global__ __launch_bounds__(128) void k_out(const float* __restrict__ Wout,
                                             const float* __restrict__ bout,
                                             float* __restrict__ out) {
    int w = blockIdx.x * 4 + (threadIdx.x >> 5);
    if (w >= NGRAPH) return;
    int lane = threadIdx.x & 31;
    float4 p = *(const float4*)(g_pool + (size_t)w * NF + lane * 4);
#pragma unroll
    for (int c = 0; c < NCLS; c++) {
        float sum = p.x * Wout[(lane * 4 + 0) * NCLS + c]
                  + p.y * Wout[(lane * 4 + 1) * NCLS + c]
                  + p.z * Wout[(lane * 4 + 2) * NCLS + c]
                  + p.w * Wout[(lane * 4 + 3) * NCLS + c];
#pragma unroll
        for (int o = 16; o > 0; o >>= 1)
            sum += __shfl_down_sync(0xffffffffu, sum, o);
        if (lane == 0) out[w * NCLS + c] = sum + bout[c];
    }
}

// ---------------- launch ----------
extern "C" void kernel_launch(void* const* d_in, const int* in_sizes, int n_in,
                              void* d_out, int out_size) {
    // Identify inputs by element count (all pairwise distinct):
    //   x: 6,400,000  edge_index: 1,600,000  batch: 50,000
    //   W: 49,152     b: 384                 W_out: 1,280   b_out: 10
    // edge_index/batch are int32 (JAX x64 disabled).
    const float* x     = nullptr;
    const int*   ei    = nullptr;
    const int*   batch = nullptr;
    const float* W     = nullptr;
    const float* b     = nullptr;
    const float* Wout  = nullptr;
    const float* bout  = nullptr;
    for (int i = 0; i < n_in; i++) {
        switch (in_sizes[i]) {
            case NNODES * NF:      x     = (const float*)d_in[i]; break;
            case 2 * NEDGES:       ei    = (const int*)d_in[i];   break;
            case NNODES:           batch = (const int*)d_in[i];   break;
            case 3 * NF * NF:      W     = (const float*)d_in[i]; break;
            case 3 * NF:           b     = (const float*)d_in[i]; break;
            case NF * NCLS:        Wout  = (const float*)d_in[i]; break;
            case NCLS:             bout  = (const float*)d_in[i]; break;
            default: break;
        }
    }
    float* out = (float*)d_out;

    const int* rowp = ei;           // source nodes j
    const int* colp = ei + NEDGES;  // target nodes i

    k_zero<<<(NGRAPH * NF + 255) / 256, 256>>>();
    k_count<<<(NEDGES + 255) / 256, 256>>>(colp);
    k_dinv<<<(NNODES + 255) / 256, 256>>>();
    k_scan_a<<<SCAN_BLOCKS, 1024>>>();
    k_scan_b<<<1, 64>>>();
    k_scan_c<<<SCAN_BLOCKS, 1024>>>();
    k_fill<<<(NEDGES + 255) / 256, 256>>>(rowp, colp);

    for (int l = 0; l < 3; l++) {
        k_gemm<<<(NNODES + 127) / 128, 256>>>(x, W, l);
        if (l < 2)
            k_gather<false><<<(NNODES + 7) / 8, 256>>>(b, l, batch);
        else
            k_gather<true><<<(NNODES + 7) / 8, 256>>>(b, l, batch);
    }

    k_out<<<NGRAPH / 4, 128>>>(Wout, bout, out);
}

// round 6
// speedup vs baseline: 1.6057x; 1.0605x over previous
#include <cuda_runtime.h>
#include <cuda_fp16.h>
#include <cstdint>

#define NNODES 50000
#define NEDGES 800000
#define NF 128
#define NGRAPH 512
#define NCLS 10
#define SCAN_BLOCKS ((NNODES + 1023) / 1024)   // 49

// ---------------- device scratch (static: no allocations allowed) ----------
__device__ float  g_h[NNODES * NF];     // layer activations (fp32)
__device__ __half g_hw[NNODES * NF];    // h @ W[l]  (fp16: halves gather traffic)
__device__ float  g_dinv[NNODES];
__device__ int    g_deg[NNODES];
__device__ int    g_off[NNODES + 1];
__device__ int    g_cur[NNODES];
__device__ int    g_row[NEDGES];
__device__ float  g_pool[NGRAPH * NF];
__device__ int    g_bsum[SCAN_BLOCKS];
__device__ int    g_boff[SCAN_BLOCKS];

// ---------------- init ----------
__global__ void k_zero() {
    int i = blockIdx.x * blockDim.x + threadIdx.x;
    if (i < NGRAPH * NF) g_pool[i] = 0.0f;
    if (i < NNODES) g_deg[i] = 0;
}

__global__ void k_count(const int* __restrict__ col) {
    int e = blockIdx.x * blockDim.x + threadIdx.x;
    if (e < NEDGES) {
        int c = col[e];
        c = min(max(c, 0), NNODES - 1);
        atomicAdd(&g_deg[c], 1);
    }
}

// ---------- scan stage A (+ dinv fused) ----------
__global__ __launch_bounds__(1024) void k_scan_a() {
    int i = blockIdx.x * 1024 + threadIdx.x;
    int lane = threadIdx.x & 31;
    int wid = threadIdx.x >> 5;
    int v = (i < NNODES) ? g_deg[i] : 0;
    if (i < NNODES) g_dinv[i] = rsqrtf((float)(v + 1));  // +1 self-loop

    int incl = v;
#pragma unroll
    for (int d = 1; d < 32; d <<= 1) {
        int t = __shfl_up_sync(0xffffffffu, incl, d);
        if (lane >= d) incl += t;
    }
    __shared__ int wsum[32];
    if (lane == 31) wsum[wid] = incl;
    __syncthreads();
    if (wid == 0) {
        int s = wsum[lane];
#pragma unroll
        for (int d = 1; d < 32; d <<= 1) {
            int t = __shfl_up_sync(0xffffffffu, s, d);
            if (lane >= d) s += t;
        }
        wsum[lane] = s;
    }
    __syncthreads();
    int warpoff = (wid > 0) ? wsum[wid - 1] : 0;
    int excl = warpoff + incl - v;
    if (i < NNODES) g_off[i] = excl;
    if (threadIdx.x == 1023) g_bsum[blockIdx.x] = warpoff + incl;
}

__global__ void k_scan_b() {
    __shared__ int s[64];
    int tid = threadIdx.x;
    int v = (tid < SCAN_BLOCKS) ? g_bsum[tid] : 0;
    s[tid] = v;
    __syncthreads();
#pragma unroll
    for (int d = 1; d < 64; d <<= 1) {
        int t = (tid >= d) ? s[tid - d] : 0;
        __syncthreads();
        s[tid] += t;
        __syncthreads();
    }
    if (tid < SCAN_BLOCKS) g_boff[tid] = s[tid] - v;
    if (tid == 0) g_off[NNODES] = NEDGES;
}

__global__ __launch_bounds__(1024) void k_scan_c() {
    int i = blockIdx.x * 1024 + threadIdx.x;
    if (i < NNODES) {
        int o = g_off[i] + g_boff[blockIdx.x];
        g_off[i] = o;
        g_cur[i] = o;
    }
}

__global__ void k_fill(const int* __restrict__ rowp,
                       const int* __restrict__ colp) {
    int e = blockIdx.x * blockDim.x + threadIdx.x;
    if (e < NEDGES) {
        int c = colp[e];
        c = min(max(c, 0), NNODES - 1);
        int r = rowp[e];
        r = min(max(r, 0), NNODES - 1);
        int p = atomicAdd(&g_cur[c], 1);
        if (p >= 0 && p < NEDGES) g_row[p] = r;
    }
}

// ---------------- tf32 helpers ----------------
__device__ __forceinline__ uint32_t f2tf32(float v) {
    uint32_t r;
    asm("cvt.rna.tf32.f32 %0, %1;" : "=r"(r) : "f"(v));
    return r;
}
__device__ __forceinline__ void split_tf32(float v, uint32_t& hi, uint32_t& lo) {
    hi = f2tf32(v);
    float hif = __uint_as_float(hi);
    lo = f2tf32(v - hif);
}
__device__ __forceinline__ void mma_tf32(float* c, const uint32_t* a,
                                         uint32_t b0, uint32_t b1) {
    asm volatile(
        "mma.sync.aligned.m16n8k8.row.col.f32.tf32.tf32.f32 "
        "{%0,%1,%2,%3}, {%4,%5,%6,%7}, {%8,%9}, {%0,%1,%2,%3};"
        : "+f"(c[0]), "+f"(c[1]), "+f"(c[2]), "+f"(c[3])
        : "r"(a[0]), "r"(a[1]), "r"(a[2]), "r"(a[3]), "r"(b0), "r"(b1));
}

// -------- GEMM (tf32 3x compensated): g_hw(fp16) = A @ W[l] ----------------
__global__ __launch_bounds__(256) void k_gemm(const float* __restrict__ x,
                                              const float* __restrict__ Wall,
                                              int layer) {
    __shared__ float As[128][36];
    __shared__ float Ws[32][136];

    const float* __restrict__ A = (layer == 0) ? x : (const float*)g_h;
    const float* __restrict__ B = Wall + (size_t)layer * NF * NF;

    int bm = blockIdx.x * 128;
    int tid = threadIdx.x;
    int warp = tid >> 5, lane = tid & 31;
    int wr = warp >> 1;
    int wc = warp & 1;
    int g = lane >> 2;
    int tig = lane & 3;

    float acc[2][8][4];
#pragma unroll
    for (int ti = 0; ti < 2; ti++)
#pragma unroll
        for (int tj = 0; tj < 8; tj++)
#pragma unroll
            for (int q = 0; q < 4; q++) acc[ti][tj][q] = 0.0f;

    for (int k0 = 0; k0 < NF; k0 += 32) {
#pragma unroll
        for (int i = 0; i < 4; i++) {
            int e = tid + i * 256;
            int row = e >> 3;
            int kq = (e & 7) * 4;
            float4 v = make_float4(0.f, 0.f, 0.f, 0.f);
            if (bm + row < NNODES)
                v = *(const float4*)(A + (size_t)(bm + row) * NF + k0 + kq);
            As[row][kq + 0] = v.x;
            As[row][kq + 1] = v.y;
            As[row][kq + 2] = v.z;
            As[row][kq + 3] = v.w;
        }
#pragma unroll
        for (int i = 0; i < 4; i++) {
            int e = tid + i * 256;
            int kr = e >> 5;
            int cq = (e & 31) * 4;
            float4 v = *(const float4*)(B + (size_t)(k0 + kr) * NF + cq);
            Ws[kr][cq + 0] = v.x;
            Ws[kr][cq + 1] = v.y;
            Ws[kr][cq + 2] = v.z;
            Ws[kr][cq + 3] = v.w;
        }
        __syncthreads();

#pragma unroll
        for (int kk = 0; kk < 32; kk += 8) {
            uint32_t ahi[2][4], alo[2][4];
#pragma unroll
            for (int ti = 0; ti < 2; ti++) {
                int r0 = wr * 32 + ti * 16 + g;
                split_tf32(As[r0][kk + tig],         ahi[ti][0], alo[ti][0]);
                split_tf32(As[r0 + 8][kk + tig],     ahi[ti][1], alo[ti][1]);
                split_tf32(As[r0][kk + tig + 4],     ahi[ti][2], alo[ti][2]);
                split_tf32(As[r0 + 8][kk + tig + 4], ahi[ti][3], alo[ti][3]);
            }
#pragma unroll
            for (int tj = 0; tj < 8; tj++) {
                int n0 = wc * 64 + tj * 8 + g;
                uint32_t bhi0, blo0, bhi1, blo1;
                split_tf32(Ws[kk + tig][n0],     bhi0, blo0);
                split_tf32(Ws[kk + tig + 4][n0], bhi1, blo1);
#pragma unroll
                for (int ti = 0; ti < 2; ti++) {
                    mma_tf32(acc[ti][tj], ahi[ti], bhi0, bhi1);
                    mma_tf32(acc[ti][tj], alo[ti], bhi0, bhi1);
                    mma_tf32(acc[ti][tj], ahi[ti], blo0, blo1);
                }
            }
        }
        __syncthreads();
    }

    // store C as fp16 (half2 per 2 cols)
#pragma unroll
    for (int ti = 0; ti < 2; ti++) {
#pragma unroll
        for (int tj = 0; tj < 8; tj++) {
            int row = bm + wr * 32 + ti * 16 + g;
            int col = wc * 64 + tj * 8 + tig * 2;
            if (row < NNODES)
                *(__half2*)(g_hw + (size_t)row * NF + col) =
                    __floats2half2_rn(acc[ti][tj][0], acc[ti][tj][1]);
            if (row + 8 < NNODES)
                *(__half2*)(g_hw + (size_t)(row + 8) * NF + col) =
                    __floats2half2_rn(acc[ti][tj][2], acc[ti][tj][3]);
        }
    }
}

// ------- gather (fp16 rows) + self-loop + bias + relu -> g_h / pool --------
template <bool DO_POOL>
__global__ __launch_bounds__(256) void k_gather(const float* __restrict__ ball,
                                                int layer,
                                                const int* __restrict__ batch) {
    int node = blockIdx.x * 8 + (threadIdx.x >> 5);
    if (node >= NNODES) return;
    int lane = threadIdx.x & 31;

    const __half* __restrict__ hw = g_hw;
    const float* __restrict__ bias = ball + layer * NF;

    float di = g_dinv[node];
    float4 acc = make_float4(0.f, 0.f, 0.f, 0.f);
    int s = g_off[node];
    int e = g_off[node + 1];
    int p = s;
    // unroll x2 for MLP
    for (; p + 1 < e; p += 2) {
        int r0 = g_row[p];
        int r1 = g_row[p + 1];
        float nm0 = di * g_dinv[r0];
        float nm1 = di * g_dinv[r1];
        uint2 raw0 = *(const uint2*)(hw + (size_t)r0 * NF + lane * 4);
        uint2 raw1 = *(const uint2*)(hw + (size_t)r1 * NF + lane * 4);
        float2 a0 = __half22float2(*(__half2*)&raw0.x);
        float2 a1 = __half22float2(*(__half2*)&raw0.y);
        float2 b0 = __half22float2(*(__half2*)&raw1.x);
        float2 b1 = __half22float2(*(__half2*)&raw1.y);
        acc.x += a0.x * nm0 + b0.x * nm1;
        acc.y += a0.y * nm0 + b0.y * nm1;
        acc.z += a1.x * nm0 + b1.x * nm1;
        acc.w += a1.y * nm0 + b1.y * nm1;
    }
    if (p < e) {
        int r0 = g_row[p];
        float nm0 = di * g_dinv[r0];
        uint2 raw0 = *(const uint2*)(hw + (size_t)r0 * NF + lane * 4);
        float2 a0 = __half22float2(*(__half2*)&raw0.x);
        float2 a1 = __half22float2(*(__half2*)&raw0.y);
        acc.x += a0.x * nm0;
        acc.y += a0.y * nm0;
        acc.z += a1.x * nm0;
        acc.w += a1.y * nm0;
    }
    // self-loop
    {
        float nm = di * di;
        uint2 raw0 = *(const uint2*)(hw + (size_t)node * NF + lane * 4);
        float2 a0 = __half22float2(*(__half2*)&raw0.x);
        float2 a1 = __half22float2(*(__half2*)&raw0.y);
        acc.x += a0.x * nm;
        acc.y += a0.y * nm;
        acc.z += a1.x * nm;
        acc.w += a1.y * nm;
    }
    float4 bb = *(const float4*)(bias + lane * 4);
    acc.x = fmaxf(acc.x + bb.x, 0.f);
    acc.y = fmaxf(acc.y + bb.y, 0.f);
    acc.z = fmaxf(acc.z + bb.z, 0.f);
    acc.w = fmaxf(acc.w + bb.w, 0.f);

    if (DO_POOL) {
        int gph = batch[node];
        gph = min(max(gph, 0), NGRAPH - 1);
        float* dst = g_pool + (size_t)gph * NF + lane * 4;
        atomicAdd(dst + 0, acc.x);
        atomicAdd(dst + 1, acc.y);
        atomicAdd(dst + 2, acc.z);
        atomicAdd(dst + 3, acc.w);
    } else {
        *(float4*)(g_h + (size_t)node * NF + lane * 4) = acc;
    }
}

// ---------------- output head ------------------
__global__ __launch_bounds__(128) void k_out(const float* __restrict__ Wout,
                                             const float* __restrict__ bout,
                                             float* __restrict__ out) {
    int w = blockIdx.x * 4 + (threadIdx.x >> 5);
    if (w >= NGRAPH) return;
    int lane = threadIdx.x & 31;
    float4 p = *(const float4*)(g_pool + (size_t)w * NF + lane * 4);
#pragma unroll
    for (int c = 0; c < NCLS; c++) {
        float sum = p.x * Wout[(lane * 4 + 0) * NCLS + c]
                  + p.y * Wout[(lane * 4 + 1) * NCLS + c]
                  + p.z * Wout[(lane * 4 + 2) * NCLS + c]
                  + p.w * Wout[(lane * 4 + 3) * NCLS + c];
#pragma unroll
        for (int o = 16; o > 0; o >>= 1)
            sum += __shfl_down_sync(0xffffffffu, sum, o);
        if (lane == 0) out[w * NCLS + c] = sum + bout[c];
    }
}

// ---------------- launch ----------
extern "C" void kernel_launch(void* const* d_in, const int* in_sizes, int n_in,
                              void* d_out, int out_size) {
    // Inputs identified by element count (all pairwise distinct).
    const float* x     = nullptr;
    const int*   ei    = nullptr;
    const int*   batch = nullptr;
    const float* W     = nullptr;
    const float* b     = nullptr;
    const float* Wout  = nullptr;
    const float* bout  = nullptr;
    for (int i = 0; i < n_in; i++) {
        switch (in_sizes[i]) {
            case NNODES * NF:      x     = (const float*)d_in[i]; break;
            case 2 * NEDGES:       ei    = (const int*)d_in[i];   break;
            case NNODES:           batch = (const int*)d_in[i];   break;
            case 3 * NF * NF:      W     = (const float*)d_in[i]; break;
            case 3 * NF:           b     = (const float*)d_in[i]; break;
            case NF * NCLS:        Wout  = (const float*)d_in[i]; break;
            case NCLS:             bout  = (const float*)d_in[i]; break;
            default: break;
        }
    }
    float* out = (float*)d_out;

    const int* rowp = ei;           // source nodes j
    const int* colp = ei + NEDGES;  // target nodes i

    k_zero<<<(NGRAPH * NF + 255) / 256, 256>>>();
    k_count<<<(NEDGES + 255) / 256, 256>>>(colp);
    k_scan_a<<<SCAN_BLOCKS, 1024>>>();
    k_scan_b<<<1, 64>>>();
    k_scan_c<<<SCAN_BLOCKS, 1024>>>();
    k_fill<<<(NEDGES + 255) / 256, 256>>>(rowp, colp);

    for (int l = 0; l < 3; l++) {
        k_gemm<<<(NNODES + 127) / 128, 256>>>(x, W, l);
        if (l < 2)
            k_gather<false><<<(NNODES + 7) / 8, 256>>>(b, l, batch);
        else
            k_gather<true><<<(NNODES + 7) / 8, 256>>>(b, l, batch);
    }

    k_out<<<NGRAPH / 4, 128>>>(Wout, bout, out);
}